// round 11
// baseline (speedup 1.0000x reference)
#include <cuda_runtime.h>
#include <cstdint>

#define OH 7
#define OW 7
#define NW 8            // warps per block
#define CH 8            // channels per warp

__global__ void __launch_bounds__(256, 8) roialign_kernel(
        const float* __restrict__ feat,
        const int* __restrict__ rois,
        float* __restrict__ out,
        int C, int H, int W) {
    const int n    = blockIdx.x;
    const int cg   = blockIdx.y;
    const int tid  = threadIdx.x;
    const int warp = tid >> 5, lane = tid & 31;
    const int cbase = (cg * NW + warp) * CH;

    const int* r = rois + n * 5;
    const int b  = __ldg(r);
    const int x1 = __ldg(r + 1), y1 = __ldg(r + 2);
    const int x2 = __ldg(r + 3), y2 = __ldg(r + 4);

    const float dy6 = (float)(y2 - y1) * 0.16666667f;
    const float dx6 = (float)(x2 - x1) * 0.16666667f;
    const float y1f = (float)y1, x1f = (float)x1;

    // ---- per-lane constants: lane = (oy, ox) on an 8x8 padded grid ----
    const int ox  = lane & 7;                 // 0..7 (7 = inactive pad)
    const int oyA = lane >> 3;                // 0..3
    const int oyB = oyA + 4;                  // 4..7 (7 = inactive pad)

    // x corners + weight
    float sx  = x1f + (float)ox * dx6;
    float x0f = floorf(sx);
    const float wx  = sx - x0f;
    const float omx = 1.0f - wx;
    const int ix0 = min(max((int)x0f, 0), W - 1);
    const int ix1 = min(ix0 + 1, W - 1);

    // y rows + weights for both halves
    float syA = y1f + (float)oyA * dy6;
    float syB = y1f + (float)oyB * dy6;
    float yA0f = floorf(syA), yB0f = floorf(syB);
    const float wyA = syA - yA0f, wyB = syB - yB0f;
    const float omyA = 1.0f - wyA, omyB = 1.0f - wyB;
    const int iyA0 = min(max((int)yA0f, 0), H - 1);
    const int rA0 = iyA0 * W;
    const int rA1 = min(iyA0 + 1, H - 1) * W;
    const int iyB0 = min(max((int)yB0f, 0), H - 1);
    const int rB0 = iyB0 * W;
    const int rB1 = min(iyB0 + 1, H - 1) * W;

    const size_t HW = (size_t)(H * W);
    const float* g  = feat + ((size_t)b * C + cbase) * HW;
    float* obase    = out + ((size_t)(n * C + cbase)) * (OH * OW);

    const bool actA = (ox < OW);
    const bool actB = (ox < OW) && (oyB < OH);

    #pragma unroll
    for (int k = 0; k < CH; k++) {
        const float* gk = g + (size_t)k * HW;
        const float a00 = __ldg(gk + rA0 + ix0);
        const float a01 = __ldg(gk + rA0 + ix1);
        const float a10 = __ldg(gk + rA1 + ix0);
        const float a11 = __ldg(gk + rA1 + ix1);
        const float b00 = __ldg(gk + rB0 + ix0);
        const float b01 = __ldg(gk + rB0 + ix1);
        const float b10 = __ldg(gk + rB1 + ix0);
        const float b11 = __ldg(gk + rB1 + ix1);

        float* o = obase + k * (OH * OW);
        if (actA)
            o[oyA * OW + ox] = (a00 * omx + a01 * wx) * omyA
                             + (a10 * omx + a11 * wx) * wyA;
        if (actB)
            o[oyB * OW + ox] = (b00 * omx + b01 * wx) * omyB
                             + (b10 * omx + b11 * wx) * wyB;
    }
}

extern "C" void kernel_launch(void* const* d_in, const int* in_sizes, int n_in,
                              void* d_out, int out_size) {
    const float* feat = (const float*)d_in[0];
    const int*   rois = (const int*)d_in[1];
    float*       out  = (float*)d_out;

    const int C = 256, H = 200, W = 200;
    const int N = in_sizes[1] / 5;

    dim3 grid(N, C / (NW * CH));
    roialign_kernel<<<grid, NW * 32>>>(feat, rois, out, C, H, W);
}

// round 12
// speedup vs baseline: 1.2532x; 1.2532x over previous
#include <cuda_runtime.h>
#include <cstdint>

#define OH 7
#define OW 7
#define NW 8            // warps per block
#define CH 8            // channels per warp

__global__ void __launch_bounds__(256) roialign_kernel(
        const float* __restrict__ feat,
        const int* __restrict__ rois,
        float* __restrict__ out,
        int C, int H, int W) {
    const int n    = blockIdx.x;
    const int cg   = blockIdx.y;
    const int tid  = threadIdx.x;
    const int warp = tid >> 5, lane = tid & 31;
    const int cbase = (cg * NW + warp) * CH;

    const int* r = rois + n * 5;
    const int b  = __ldg(r);
    const int x1 = __ldg(r + 1), y1 = __ldg(r + 2);
    const int x2 = __ldg(r + 3), y2 = __ldg(r + 4);

    const float dy6 = (float)(y2 - y1) * 0.16666667f;
    const float dx6 = (float)(x2 - x1) * 0.16666667f;
    const float y1f = (float)y1, x1f = (float)x1;

    // ---- per-lane constants: lane = (oy, ox) on an 8x8 padded grid ----
    const int ox  = lane & 7;                 // 0..7 (7 = inactive pad)
    const int oyA = lane >> 3;                // 0..3
    const int oyB = oyA + 4;                  // 4..7 (7 = inactive pad)

    float sx  = x1f + (float)ox * dx6;
    float x0f = floorf(sx);
    const float wx  = sx - x0f;
    const float omx = 1.0f - wx;
    const int ix0 = min(max((int)x0f, 0), W - 1);
    const int ix1 = min(ix0 + 1, W - 1);

    float syA = y1f + (float)oyA * dy6;
    float syB = y1f + (float)oyB * dy6;
    float yA0f = floorf(syA), yB0f = floorf(syB);
    const float wyA = syA - yA0f, wyB = syB - yB0f;
    const float omyA = 1.0f - wyA, omyB = 1.0f - wyB;
    const int iyA0 = min(max((int)yA0f, 0), H - 1);
    const int iyA1 = min(iyA0 + 1, H - 1);
    const int iyB0 = min(max((int)yB0f, 0), H - 1);
    const int iyB1 = min(iyB0 + 1, H - 1);

    // 8 fixed per-lane gather offsets (precombined: best known config)
    const int oA00 = iyA0 * W + ix0, oA01 = iyA0 * W + ix1;
    const int oA10 = iyA1 * W + ix0, oA11 = iyA1 * W + ix1;
    const int oB00 = iyB0 * W + ix0, oB01 = iyB0 * W + ix1;
    const int oB10 = iyB1 * W + ix0, oB11 = iyB1 * W + ix1;

    const size_t HW = (size_t)(H * W);
    const float* g  = feat + ((size_t)b * C + cbase) * HW;
    float* obase    = out + ((size_t)(n * C + cbase)) * (OH * OW);

    const bool actA = (ox < OW);
    const bool actB = (ox < OW) && (oyB < OH);

    // ---- register double-buffer: prefetch ch k+1 while computing ch k ----
    float c0, c1, c2, c3, c4, c5, c6, c7;   // current
    float p0, p1, p2, p3, p4, p5, p6, p7;   // prefetch

    {   // prologue: load channel 0
        const float* gk = g;
        c0 = __ldg(gk + oA00); c1 = __ldg(gk + oA01);
        c2 = __ldg(gk + oA10); c3 = __ldg(gk + oA11);
        c4 = __ldg(gk + oB00); c5 = __ldg(gk + oB01);
        c6 = __ldg(gk + oB10); c7 = __ldg(gk + oB11);
    }

    #pragma unroll
    for (int k = 0; k < CH; k++) {
        if (k + 1 < CH) {   // prefetch next channel before consuming current
            const float* gk = g + (size_t)(k + 1) * HW;
            p0 = __ldg(gk + oA00); p1 = __ldg(gk + oA01);
            p2 = __ldg(gk + oA10); p3 = __ldg(gk + oA11);
            p4 = __ldg(gk + oB00); p5 = __ldg(gk + oB01);
            p6 = __ldg(gk + oB10); p7 = __ldg(gk + oB11);
        }

        float* o = obase + k * (OH * OW);
        if (actA)
            o[oyA * OW + ox] = (c0 * omx + c1 * wx) * omyA
                             + (c2 * omx + c3 * wx) * wyA;
        if (actB)
            o[oyB * OW + ox] = (c4 * omx + c5 * wx) * omyB
                             + (c6 * omx + c7 * wx) * wyB;

        c0 = p0; c1 = p1; c2 = p2; c3 = p3;
        c4 = p4; c5 = p5; c6 = p6; c7 = p7;
    }
}

extern "C" void kernel_launch(void* const* d_in, const int* in_sizes, int n_in,
                              void* d_out, int out_size) {
    const float* feat = (const float*)d_in[0];
    const int*   rois = (const int*)d_in[1];
    float*       out  = (float*)d_out;

    const int C = 256, H = 200, W = 200;
    const int N = in_sizes[1] / 5;

    dim3 grid(N, C / (NW * CH));
    roialign_kernel<<<grid, NW * 32>>>(feat, rois, out, C, H, W);
}